// round 2
// baseline (speedup 1.0000x reference)
#include <cuda_runtime.h>
#include <cstdint>

// Problem constants
#define NB 32
#define SEQ 64
#define EMB 512
#define NH 4
#define HDIM 128
#define NTOK (NB*SEQ)          // 2048

// ---------------- device scratch (no runtime alloc allowed) ----------------
__device__ float g_qkv  [NTOK*1536];
__device__ float g_attn [NB*NH*SEQ*SEQ];
__device__ float g_attno[NTOK*EMB];
__device__ float g_xres [NTOK*1024];
__device__ float g_h    [NTOK*EMB];
__device__ float g_ln1  [NTOK*EMB];
__device__ float g_h2   [NTOK*EMB];
__device__ float g_y1   [NTOK*128];
__device__ float g_y2   [NTOK*128];

// ---------------- generic SGEMM: C[m,n] = sum_k A[m,k]*B[n,k] (+bias) ------
// mode 0: C = acc + bias
// mode 1: C = resid + relu(acc + bias)
__global__ void __launch_bounds__(256) gemm_nt(
    const float* __restrict__ A, int lda,
    const float* __restrict__ B, int ldb,
    float* __restrict__ C, int ldc,
    const float* __restrict__ bias,
    const float* __restrict__ resid, int ldr,
    int K, int mode)
{
    __shared__ float As[16][64];
    __shared__ float Bs[16][64];
    int bm = blockIdx.y << 6, bn = blockIdx.x << 6;
    int tid = threadIdx.x;
    int ty = tid >> 4, tx = tid & 15;
    int lr = tid >> 2, lc4 = (tid & 3) << 2;
    float acc[4][4] = {};
    const float* Ap = A + (size_t)(bm + lr) * lda + lc4;
    const float* Bp = B + (size_t)(bn + lr) * ldb + lc4;
    for (int k0 = 0; k0 < K; k0 += 16) {
        float4 av = *(const float4*)(Ap + k0);
        float4 bv = *(const float4*)(Bp + k0);
        As[lc4+0][lr]=av.x; As[lc4+1][lr]=av.y; As[lc4+2][lr]=av.z; As[lc4+3][lr]=av.w;
        Bs[lc4+0][lr]=bv.x; Bs[lc4+1][lr]=bv.y; Bs[lc4+2][lr]=bv.z; Bs[lc4+3][lr]=bv.w;
        __syncthreads();
        #pragma unroll
        for (int k = 0; k < 16; k++) {
            float4 a4 = *(const float4*)&As[k][ty<<2];
            float4 b4 = *(const float4*)&Bs[k][tx<<2];
            float aa[4] = {a4.x,a4.y,a4.z,a4.w};
            float bb[4] = {b4.x,b4.y,b4.z,b4.w};
            #pragma unroll
            for (int i = 0; i < 4; i++)
                #pragma unroll
                for (int j = 0; j < 4; j++)
                    acc[i][j] = fmaf(aa[i], bb[j], acc[i][j]);
        }
        __syncthreads();
    }
    #pragma unroll
    for (int i = 0; i < 4; i++) {
        int m = bm + (ty<<2) + i;
        #pragma unroll
        for (int j = 0; j < 4; j++) {
            int n = bn + (tx<<2) + j;
            float v = acc[i][j];
            if (bias) v += bias[n];
            if (mode == 1) v = resid[(size_t)m*ldr + n] + fmaxf(v, 0.f);
            C[(size_t)m*ldc + n] = v;
        }
    }
}

// -------- x1 path: Gram -> -L2/T softmax -> x1 = attn @ x (per batch) ------
__global__ void __launch_bounds__(256) x1_kernel(
    const float* __restrict__ x, float* __restrict__ a_out, float* __restrict__ xres)
{
    extern __shared__ float sm[];
    const int STR = 513;                 // pad: conflict-free column reads
    float* xs   = sm;                    // 64*513
    float* sa   = xs + 64*STR;           // 64*64 Gram -> attn
    float* snrm = sa + 4096;             // 64 diag
    int b = blockIdx.x, tid = threadIdx.x;
    const float* xb = x + (size_t)b*SEQ*EMB;
    for (int i = tid; i < SEQ*EMB; i += 256)
        xs[(i>>9)*STR + (i&511)] = xb[i];
    __syncthreads();
    int w = tid>>5, lane = tid&31, f0 = w*8;
    float acc0[8] = {}, acc1[8] = {};
    for (int e = 0; e < EMB; e++) {
        float gv0 = xs[lane*STR + e], gv1 = xs[(lane+32)*STR + e];
        #pragma unroll
        for (int i = 0; i < 8; i++) {
            float fv = xs[(f0+i)*STR + e];
            acc0[i] = fmaf(fv, gv0, acc0[i]);
            acc1[i] = fmaf(fv, gv1, acc1[i]);
        }
    }
    #pragma unroll
    for (int i = 0; i < 8; i++) {
        sa[(f0+i)*64 + lane]      = acc0[i];
        sa[(f0+i)*64 + lane + 32] = acc1[i];
    }
    __syncthreads();
    if (tid < 64) snrm[tid] = sa[tid*65];
    __syncthreads();
    const float invT = 1.f/13.544f;
    float* ab = a_out + (size_t)b*4096;
    #pragma unroll
    for (int i = 0; i < 8; i++) {
        int f = f0 + i;
        float nf = snrm[f];
        float s0 = (2.f*sa[f*64+lane]    - nf - snrm[lane])    * invT;
        float s1 = (2.f*sa[f*64+lane+32] - nf - snrm[lane+32]) * invT;
        float m = fmaxf(s0, s1);
        for (int o = 16; o; o >>= 1) m = fmaxf(m, __shfl_xor_sync(0xffffffffu, m, o));
        float e0 = __expf(s0 - m), e1 = __expf(s1 - m);
        float sum = e0 + e1;
        for (int o = 16; o; o >>= 1) sum += __shfl_xor_sync(0xffffffffu, sum, o);
        float r = 1.f/sum; e0 *= r; e1 *= r;
        sa[f*64+lane] = e0; sa[f*64+lane+32] = e1;
        ab[f*64+lane] = e0; ab[f*64+lane+32] = e1;
    }
    __syncwarp();
    // x1[f,e] = sum_g a[f,g]*x[g,e]  (each warp: its own 8 f-rows)
    for (int ec = 0; ec < 4; ec++) {
        float acc[8][4];
        #pragma unroll
        for (int i = 0; i < 8; i++) { acc[i][0]=acc[i][1]=acc[i][2]=acc[i][3]=0.f; }
        for (int g = 0; g < 64; g++) {
            float vv[4];
            #pragma unroll
            for (int j = 0; j < 4; j++) vv[j] = xs[g*STR + ec*128 + j*32 + lane];
            #pragma unroll
            for (int i = 0; i < 8; i++) {
                float av = sa[(f0+i)*64 + g];
                #pragma unroll
                for (int j = 0; j < 4; j++) acc[i][j] = fmaf(av, vv[j], acc[i][j]);
            }
        }
        #pragma unroll
        for (int i = 0; i < 8; i++)
            #pragma unroll
            for (int j = 0; j < 4; j++)
                xres[(size_t)(b*SEQ + f0 + i)*1024 + ec*128 + j*32 + lane] = acc[i][j];
    }
}

// -------------- MHA core: per (b,h): softmax(QK^T/sqrt(hd)) @ V ------------
__global__ void __launch_bounds__(256) mha_kernel(
    const float* __restrict__ qkv, float* __restrict__ attn_g, float* __restrict__ attno)
{
    extern __shared__ float sm[];
    const int STR = 129;
    float* qs = sm;
    float* ks = qs + 64*STR;
    float* vs = ks + 64*STR;
    float* sa = vs + 64*STR;             // 64*64 attn
    int b = blockIdx.x >> 2, h = blockIdx.x & 3;
    int tid = threadIdx.x;
    const float* base = qkv + (size_t)b*SEQ*1536 + h*128;
    for (int i = tid; i < 64*128; i += 256) {
        int r = i >> 7, c = i & 127;
        const float* rp = base + (size_t)r*1536;
        qs[r*STR+c] = rp[c];
        ks[r*STR+c] = rp[512 + c];
        vs[r*STR+c] = rp[1024 + c];
    }
    __syncthreads();
    int w = tid>>5, lane = tid&31, f0 = w*8;
    float acc0[8] = {}, acc1[8] = {};
    for (int e = 0; e < 128; e++) {
        float k0 = ks[lane*STR + e], k1 = ks[(lane+32)*STR + e];
        #pragma unroll
        for (int i = 0; i < 8; i++) {
            float qv = qs[(f0+i)*STR + e];
            acc0[i] = fmaf(qv, k0, acc0[i]);
            acc1[i] = fmaf(qv, k1, acc1[i]);
        }
    }
    const float scale = 0.088388347648318447f;  // 1/sqrt(128)
    float* ab = attn_g + (size_t)(b*4 + h)*4096;
    #pragma unroll
    for (int i = 0; i < 8; i++) {
        float s0 = acc0[i]*scale, s1 = acc1[i]*scale;
        float m = fmaxf(s0, s1);
        for (int o = 16; o; o >>= 1) m = fmaxf(m, __shfl_xor_sync(0xffffffffu, m, o));
        float e0 = __expf(s0 - m), e1 = __expf(s1 - m);
        float sum = e0 + e1;
        for (int o = 16; o; o >>= 1) sum += __shfl_xor_sync(0xffffffffu, sum, o);
        float r = 1.f/sum; e0 *= r; e1 *= r;
        int f = f0 + i;
        sa[f*64+lane] = e0; sa[f*64+lane+32] = e1;
        ab[f*64+lane] = e0; ab[f*64+lane+32] = e1;
    }
    __syncwarp();
    float acc[8][4];
    #pragma unroll
    for (int i = 0; i < 8; i++) { acc[i][0]=acc[i][1]=acc[i][2]=acc[i][3]=0.f; }
    for (int g = 0; g < 64; g++) {
        float vv[4];
        #pragma unroll
        for (int j = 0; j < 4; j++) vv[j] = vs[g*STR + j*32 + lane];
        #pragma unroll
        for (int i = 0; i < 8; i++) {
            float av = sa[(f0+i)*64 + g];
            #pragma unroll
            for (int j = 0; j < 4; j++) acc[i][j] = fmaf(av, vv[j], acc[i][j]);
        }
    }
    #pragma unroll
    for (int i = 0; i < 8; i++)
        #pragma unroll
        for (int j = 0; j < 4; j++)
            attno[(size_t)(b*SEQ + f0 + i)*EMB + h*128 + j*32 + lane] = acc[i][j];
}

// ------------- mean over heads of attn -> x2_attn ---------------------------
__global__ void attn_mean_kernel(const float* __restrict__ attn, float* __restrict__ out)
{
    int i = blockIdx.x*256 + threadIdx.x;     // 131072 total
    int b = i >> 12, r = i & 4095;
    const float* p = attn + (size_t)b*4*4096 + r;
    out[i] = 0.25f*(p[0] + p[4096] + p[8192] + p[12288]);
}

// ------------- layernorm over last dim (512) --------------------------------
__global__ void __launch_bounds__(128) ln_kernel(
    const float* __restrict__ in, const float* __restrict__ gw,
    const float* __restrict__ bw, float* __restrict__ out)
{
    int t = blockIdx.x, tid = threadIdx.x;
    const float* r = in + (size_t)t*EMB;
    float v[4];
    #pragma unroll
    for (int i = 0; i < 4; i++) v[i] = r[tid + i*128];
    float s  = v[0]+v[1]+v[2]+v[3];
    float s2 = v[0]*v[0]+v[1]*v[1]+v[2]*v[2]+v[3]*v[3];
    for (int o = 16; o; o >>= 1) {
        s  += __shfl_xor_sync(0xffffffffu, s,  o);
        s2 += __shfl_xor_sync(0xffffffffu, s2, o);
    }
    __shared__ float rs[4], rs2[4];
    int w = tid>>5, lane = tid&31;
    if (lane == 0) { rs[w] = s; rs2[w] = s2; }
    __syncthreads();
    s  = rs[0]+rs[1]+rs[2]+rs[3];
    s2 = rs2[0]+rs2[1]+rs2[2]+rs2[3];
    float mean = s*(1.f/512.f);
    float var  = s2*(1.f/512.f) - mean*mean;
    float inv  = rsqrtf(var + 1e-5f);
    #pragma unroll
    for (int i = 0; i < 4; i++) {
        int c = tid + i*128;
        out[(size_t)t*EMB + c] = (v[i]-mean)*inv*gw[c] + bw[c];
    }
}

// ------------- pair MLPs: diff1/diff2 via factored y = x@W1^T ---------------
__global__ void __launch_bounds__(256) pair_kernel(
    const float* __restrict__ y1, const float* __restrict__ y2,
    const float* __restrict__ a1, const float* __restrict__ a2,
    const float* __restrict__ b11, const float* __restrict__ w12, const float* __restrict__ b12,
    const float* __restrict__ b21, const float* __restrict__ w22, const float* __restrict__ b22,
    float* __restrict__ o1, float* __restrict__ o2)
{
    extern __shared__ float sm[];
    float* sy1 = sm;            // 64*128
    float* sy2 = sy1 + 8192;    // 64*128
    float* sb1 = sy2 + 8192;
    float* sw1 = sb1 + 128;
    float* sb2 = sw1 + 128;
    float* sw2 = sb2 + 128;
    int b = blockIdx.x, tid = threadIdx.x;
    for (int i = tid; i < 8192; i += 256) {
        sy1[i] = y1[(size_t)b*8192 + i];
        sy2[i] = y2[(size_t)b*8192 + i];
    }
    if (tid < 128) { sb1[tid]=b11[tid]; sw1[tid]=w12[tid]; sb2[tid]=b21[tid]; sw2[tid]=w22[tid]; }
    __syncthreads();
    float bias1 = b12[0], bias2 = b22[0];
    int w = tid>>5, lane = tid&31;
    for (int p = w; p < 4096; p += 8) {
        int f = p >> 6, g = p & 63;
        float av1 = a1[(size_t)b*4096 + p];
        float av2 = a2[(size_t)b*4096 + p];
        const float* yg1 = sy1 + g*128; const float* yf1 = sy1 + f*128;
        const float* yg2 = sy2 + g*128; const float* yf2 = sy2 + f*128;
        float acc1 = 0.f, acc2 = 0.f;
        #pragma unroll
        for (int j = 0; j < 4; j++) {
            int c = j*32 + lane;
            float h1 = fmaf(av1, yg1[c]-yf1[c], sb1[c]);
            acc1 = fmaf(fmaxf(h1, 0.f), sw1[c], acc1);
            float h2 = fmaf(av2, yg2[c]-yf2[c], sb2[c]);
            acc2 = fmaf(fmaxf(h2, 0.f), sw2[c], acc2);
        }
        for (int o = 16; o; o >>= 1) {
            acc1 += __shfl_xor_sync(0xffffffffu, acc1, o);
            acc2 += __shfl_xor_sync(0xffffffffu, acc2, o);
        }
        if (lane == 0) {
            o1[(size_t)b*4096 + p] = fmaxf(acc1 + bias1, 0.f);
            o2[(size_t)b*4096 + p] = fmaxf(acc2 + bias2, 0.f);
        }
    }
}

// ---------------------------------------------------------------------------
extern "C" void kernel_launch(void* const* d_in, const int* in_sizes, int n_in,
                              void* d_out, int out_size)
{
    const float* x    = (const float*)d_in[0];
    const float* Wqkv = (const float*)d_in[1];
    const float* bqkv = (const float*)d_in[2];
    const float* Wo   = (const float*)d_in[3];
    const float* bo   = (const float*)d_in[4];
    const float* W1   = (const float*)d_in[5];
    const float* b1   = (const float*)d_in[6];
    const float* W2   = (const float*)d_in[7];
    const float* b2   = (const float*)d_in[8];
    const float* g1   = (const float*)d_in[9];
    const float* be1  = (const float*)d_in[10];
    const float* g2   = (const float*)d_in[11];
    const float* be2  = (const float*)d_in[12];
    const float* d1W1 = (const float*)d_in[13];
    const float* d1b1 = (const float*)d_in[14];
    const float* d1W2 = (const float*)d_in[15];
    const float* d1b2 = (const float*)d_in[16];
    const float* d2W1 = (const float*)d_in[17];
    const float* d2b1 = (const float*)d_in[18];
    const float* d2W2 = (const float*)d_in[19];
    const float* d2b2 = (const float*)d_in[20];

    float* out = (float*)d_out;
    float* A1 = out + 1048576;   // x1_attn (N,1,S,S)
    float* A2 = A1 + 131072;     // x2_attn
    float* D1 = A2 + 131072;     // diff1
    float* D2 = D1 + 131072;     // diff2

    float *p_qkv, *p_attn, *p_attno, *p_xres, *p_h, *p_ln1, *p_h2, *p_y1, *p_y2;
    cudaGetSymbolAddress((void**)&p_qkv,   g_qkv);
    cudaGetSymbolAddress((void**)&p_attn,  g_attn);
    cudaGetSymbolAddress((void**)&p_attno, g_attno);
    cudaGetSymbolAddress((void**)&p_xres,  g_xres);
    cudaGetSymbolAddress((void**)&p_h,     g_h);
    cudaGetSymbolAddress((void**)&p_ln1,   g_ln1);
    cudaGetSymbolAddress((void**)&p_h2,    g_h2);
    cudaGetSymbolAddress((void**)&p_y1,    g_y1);
    cudaGetSymbolAddress((void**)&p_y2,    g_y2);

    const int X1_SMEM   = (64*513 + 4096 + 64) * 4;   // 147968
    const int MHA_SMEM  = (3*64*129 + 4096) * 4;      // 115456
    const int PAIR_SMEM = (2*8192 + 4*128) * 4;       // 67584
    cudaFuncSetAttribute(x1_kernel,   cudaFuncAttributeMaxDynamicSharedMemorySize, X1_SMEM);
    cudaFuncSetAttribute(mha_kernel,  cudaFuncAttributeMaxDynamicSharedMemorySize, MHA_SMEM);
    cudaFuncSetAttribute(pair_kernel, cudaFuncAttributeMaxDynamicSharedMemorySize, PAIR_SMEM);

    // 1. qkv = x @ Wqkv^T + bqkv
    gemm_nt<<<dim3(24,32), 256>>>(x, 512, Wqkv, 512, p_qkv, 1536, bqkv, nullptr, 0, 512, 0);
    // 2. x1 branch: Gram -> softmax -> x1 (writes xres cols [0,512)) + x1_attn to out
    x1_kernel<<<32, 256, X1_SMEM>>>(x, A1, p_xres);
    // 3. per-head attention
    mha_kernel<<<128, 256, MHA_SMEM>>>(p_qkv, p_attn, p_attno);
    // 4. mean over heads -> x2_attn
    attn_mean_kernel<<<512, 256>>>(p_attn, A2);
    // 5. out-proj -> xres cols [512,1024)
    gemm_nt<<<dim3(8,32), 256>>>(p_attno, 512, Wo, 512, p_xres + 512, 1024, bo, nullptr, 0, 512, 0);
    // 6. fc1: h = x + relu(xres @ W1^T + b1)
    gemm_nt<<<dim3(8,32), 256>>>(p_xres, 1024, W1, 1024, p_h, 512, b1, x, 512, 1024, 1);
    // 7. LN1
    ln_kernel<<<2048, 128>>>(p_h, g1, be1, p_ln1);
    // 8. fc2: h2 = ln1 + relu(ln1 @ W2^T + b2)
    gemm_nt<<<dim3(8,32), 256>>>(p_ln1, 512, W2, 512, p_h2, 512, b2, p_ln1, 512, 512, 1);
    // 9. LN2 -> out
    ln_kernel<<<2048, 128>>>(p_h2, g2, be2, out);
    // 10. factored pair-MLP projections: y = x @ dW1^T (bias applied later)
    gemm_nt<<<dim3(2,32), 256>>>(x, 512, d1W1, 512, p_y1, 128, nullptr, nullptr, 0, 512, 0);
    gemm_nt<<<dim3(2,32), 256>>>(x, 512, d2W1, 512, p_y2, 128, nullptr, nullptr, 0, 512, 0);
    // 11. pair MLPs -> diff1/diff2
    pair_kernel<<<32, 256, PAIR_SMEM>>>(p_y1, p_y2, A1, A2,
                                        d1b1, d1W2, d1b2, d2b1, d2W2, d2b2, D1, D2);
}

// round 5
// speedup vs baseline: 2.0223x; 2.0223x over previous
#include <cuda_runtime.h>
#include <cstdint>

// Problem constants
#define NB 32
#define SEQ 64
#define EMB 512
#define NH 4
#define NTOK (NB*SEQ)          // 2048
#define NBIG 1792              // 1536 (qkv) + 128 (d1W1) + 128 (d2W1)

// ---------------- device scratch (no runtime alloc allowed) ----------------
__device__ float g_big  [NTOK*NBIG];     // qkv | y1 | y2
__device__ float g_wbig [NBIG*EMB];
__device__ float g_bbig [NBIG];
__device__ float g_attn [NB*NH*SEQ*SEQ];
__device__ float g_attno[NTOK*EMB];
__device__ float g_xres [NTOK*1024];
__device__ float g_h    [NTOK*EMB];
__device__ float g_ln1  [NTOK*EMB];
__device__ float g_h2   [NTOK*EMB];

// ---- bias assembly: bqkv | zeros(256) --------------------------------------
__global__ void pack_bias_kernel(const float* __restrict__ bqkv, float* __restrict__ bbig)
{
    int i = blockIdx.x*256 + threadIdx.x;
    if (i < NBIG) bbig[i] = (i < 1536) ? bqkv[i] : 0.f;
}

// ---------------- SGEMM: C[m,n] = sum_k A[m,k]*B[n,k] (+bias) --------------
// BM=128, BN=64, BK=16, 256 threads, 8x4 per thread, double-buffered.
// mode 0: C = acc + bias ; mode 1: C = resid + relu(acc + bias)
__global__ void __launch_bounds__(256, 2) gemm_nt(
    const float* __restrict__ A, int lda,
    const float* __restrict__ B, int ldb,
    float* __restrict__ C, int ldc,
    const float* __restrict__ bias,
    const float* __restrict__ resid, int ldr,
    int K, int mode)
{
    __shared__ float As[2][16][128];
    __shared__ float Bs[2][16][64];
    int bm = blockIdx.y << 7, bn = blockIdx.x << 6;
    int tid = threadIdx.x;
    int ty = tid >> 4;          // 0..15  (m group: 8 rows)
    int tx = tid & 15;          // 0..15  (n group: 4 cols)
    int lr = tid >> 2;          // 0..63
    int lk = (tid & 3) << 2;    // 0,4,8,12

    const float* Ap0 = A + (size_t)(bm + lr) * lda + lk;
    const float* Ap1 = Ap0 + (size_t)64 * lda;
    const float* Bp  = B + (size_t)(bn + lr) * ldb + lk;

    float acc[8][4] = {};

    // prologue: chunk 0 -> buffer 0
    {
        float4 a0 = *(const float4*)Ap0;
        float4 a1 = *(const float4*)Ap1;
        float4 b0 = *(const float4*)Bp;
        As[0][lk+0][lr]    = a0.x; As[0][lk+1][lr]    = a0.y;
        As[0][lk+2][lr]    = a0.z; As[0][lk+3][lr]    = a0.w;
        As[0][lk+0][lr+64] = a1.x; As[0][lk+1][lr+64] = a1.y;
        As[0][lk+2][lr+64] = a1.z; As[0][lk+3][lr+64] = a1.w;
        Bs[0][lk+0][lr] = b0.x; Bs[0][lk+1][lr] = b0.y;
        Bs[0][lk+2][lr] = b0.z; Bs[0][lk+3][lr] = b0.w;
    }
    __syncthreads();

    int nk = K >> 4;
    for (int c = 0; c < nk; ++c) {
        int cur = c & 1;
        float4 na0, na1, nb0;
        bool more = (c + 1 < nk);
        if (more) {
            int ko = (c + 1) << 4;
            na0 = *(const float4*)(Ap0 + ko);
            na1 = *(const float4*)(Ap1 + ko);
            nb0 = *(const float4*)(Bp  + ko);
        }
        #pragma unroll
        for (int k = 0; k < 16; ++k) {
            float4 af0 = *(const float4*)&As[cur][k][ty*8];
            float4 af1 = *(const float4*)&As[cur][k][ty*8+4];
            float4 bf  = *(const float4*)&Bs[cur][k][tx*4];
            float aa[8] = {af0.x,af0.y,af0.z,af0.w,af1.x,af1.y,af1.z,af1.w};
            float bb[4] = {bf.x,bf.y,bf.z,bf.w};
            #pragma unroll
            for (int i = 0; i < 8; i++)
                #pragma unroll
                for (int j = 0; j < 4; j++)
                    acc[i][j] = fmaf(aa[i], bb[j], acc[i][j]);
        }
        if (more) {
            int nb = cur ^ 1;
            As[nb][lk+0][lr]    = na0.x; As[nb][lk+1][lr]    = na0.y;
            As[nb][lk+2][lr]    = na0.z; As[nb][lk+3][lr]    = na0.w;
            As[nb][lk+0][lr+64] = na1.x; As[nb][lk+1][lr+64] = na1.y;
            As[nb][lk+2][lr+64] = na1.z; As[nb][lk+3][lr+64] = na1.w;
            Bs[nb][lk+0][lr] = nb0.x; Bs[nb][lk+1][lr] = nb0.y;
            Bs[nb][lk+2][lr] = nb0.z; Bs[nb][lk+3][lr] = nb0.w;
            __syncthreads();
        }
    }

    // epilogue
    int n = bn + tx*4;
    float4 bv = make_float4(0.f,0.f,0.f,0.f);
    if (bias) bv = *(const float4*)&bias[n];
    #pragma unroll
    for (int i = 0; i < 8; i++) {
        int m = bm + ty*8 + i;
        float4 v = make_float4(acc[i][0]+bv.x, acc[i][1]+bv.y,
                               acc[i][2]+bv.z, acc[i][3]+bv.w);
        if (mode == 1) {
            float4 r = *(const float4*)&resid[(size_t)m*ldr + n];
            v.x = r.x + fmaxf(v.x, 0.f); v.y = r.y + fmaxf(v.y, 0.f);
            v.z = r.z + fmaxf(v.z, 0.f); v.w = r.w + fmaxf(v.w, 0.f);
        }
        *(float4*)&C[(size_t)m*ldc + n] = v;
    }
}

// -------- x1 path: Gram -> -L2/T softmax -> x1 = attn @ x (per batch) ------
__global__ void __launch_bounds__(256) x1_kernel(
    const float* __restrict__ x, float* __restrict__ a_out, float* __restrict__ xres)
{
    extern __shared__ float sm[];
    const int STR = 513;                 // pad: conflict-free column reads
    float* xs   = sm;                    // 64*513
    float* sa   = xs + 64*STR;           // 64*64 Gram -> attn
    float* snrm = sa + 4096;             // 64 diag
    int b = blockIdx.x, tid = threadIdx.x;
    const float* xb = x + (size_t)b*SEQ*EMB;
    for (int i = tid; i < SEQ*EMB; i += 256)
        xs[(i>>9)*STR + (i&511)] = xb[i];
    __syncthreads();
    int w = tid>>5, lane = tid&31, f0 = w*8;
    float acc0[8] = {}, acc1[8] = {};
    for (int e = 0; e < EMB; e++) {
        float gv0 = xs[lane*STR + e], gv1 = xs[(lane+32)*STR + e];
        #pragma unroll
        for (int i = 0; i < 8; i++) {
            float fv = xs[(f0+i)*STR + e];
            acc0[i] = fmaf(fv, gv0, acc0[i]);
            acc1[i] = fmaf(fv, gv1, acc1[i]);
        }
    }
    #pragma unroll
    for (int i = 0; i < 8; i++) {
        sa[(f0+i)*64 + lane]      = acc0[i];
        sa[(f0+i)*64 + lane + 32] = acc1[i];
    }
    __syncthreads();
    if (tid < 64) snrm[tid] = sa[tid*65];
    __syncthreads();
    const float invT = 1.f/13.544f;
    float* ab = a_out + (size_t)b*4096;
    #pragma unroll
    for (int i = 0; i < 8; i++) {
        int f = f0 + i;
        float nf = snrm[f];
        float s0 = (2.f*sa[f*64+lane]    - nf - snrm[lane])    * invT;
        float s1 = (2.f*sa[f*64+lane+32] - nf - snrm[lane+32]) * invT;
        float m = fmaxf(s0, s1);
        for (int o = 16; o; o >>= 1) m = fmaxf(m, __shfl_xor_sync(0xffffffffu, m, o));
        float e0 = __expf(s0 - m), e1 = __expf(s1 - m);
        float sum = e0 + e1;
        for (int o = 16; o; o >>= 1) sum += __shfl_xor_sync(0xffffffffu, sum, o);
        float r = 1.f/sum; e0 *= r; e1 *= r;
        sa[f*64+lane] = e0; sa[f*64+lane+32] = e1;
        ab[f*64+lane] = e0; ab[f*64+lane+32] = e1;
    }
    __syncwarp();
    // x1[f,e] = sum_g a[f,g]*x[g,e]  (each warp: its own 8 f-rows)
    for (int ec = 0; ec < 4; ec++) {
        float acc[8][4];
        #pragma unroll
        for (int i = 0; i < 8; i++) { acc[i][0]=acc[i][1]=acc[i][2]=acc[i][3]=0.f; }
        for (int g = 0; g < 64; g++) {
            float vv[4];
            #pragma unroll
            for (int j = 0; j < 4; j++) vv[j] = xs[g*STR + ec*128 + j*32 + lane];
            #pragma unroll
            for (int i = 0; i < 8; i++) {
                float av = sa[(f0+i)*64 + g];
                #pragma unroll
                for (int j = 0; j < 4; j++) acc[i][j] = fmaf(av, vv[j], acc[i][j]);
            }
        }
        #pragma unroll
        for (int i = 0; i < 8; i++)
            #pragma unroll
            for (int j = 0; j < 4; j++)
                xres[(size_t)(b*SEQ + f0 + i)*1024 + ec*128 + j*32 + lane] = acc[i][j];
    }
}

// -------------- MHA core: per (b,h): softmax(QK^T/sqrt(hd)) @ V ------------
__global__ void __launch_bounds__(256) mha_kernel(
    const float* __restrict__ qkv, float* __restrict__ attn_g, float* __restrict__ attno)
{
    extern __shared__ float sm[];
    const int STR = 129;
    float* qs = sm;
    float* ks = qs + 64*STR;
    float* vs = ks + 64*STR;
    float* sa = vs + 64*STR;             // 64*64 attn
    int b = blockIdx.x >> 2, h = blockIdx.x & 3;
    int tid = threadIdx.x;
    const float* base = qkv + (size_t)b*SEQ*NBIG + h*128;
    for (int i = tid; i < 64*128; i += 256) {
        int r = i >> 7, c = i & 127;
        const float* rp = base + (size_t)r*NBIG;
        qs[r*STR+c] = rp[c];
        ks[r*STR+c] = rp[512 + c];
        vs[r*STR+c] = rp[1024 + c];
    }
    __syncthreads();
    int w = tid>>5, lane = tid&31, f0 = w*8;
    float acc0[8] = {}, acc1[8] = {};
    for (int e = 0; e < 128; e++) {
        float k0 = ks[lane*STR + e], k1 = ks[(lane+32)*STR + e];
        #pragma unroll
        for (int i = 0; i < 8; i++) {
            float qv = qs[(f0+i)*STR + e];
            acc0[i] = fmaf(qv, k0, acc0[i]);
            acc1[i] = fmaf(qv, k1, acc1[i]);
        }
    }
    const float scale = 0.088388347648318447f;  // 1/sqrt(128)
    float* ab = attn_g + (size_t)(b*4 + h)*4096;
    #pragma unroll
    for (int i = 0; i < 8; i++) {
        float s0 = acc0[i]*scale, s1 = acc1[i]*scale;
        float m = fmaxf(s0, s1);
        for (int o = 16; o; o >>= 1) m = fmaxf(m, __shfl_xor_sync(0xffffffffu, m, o));
        float e0 = __expf(s0 - m), e1 = __expf(s1 - m);
        float sum = e0 + e1;
        for (int o = 16; o; o >>= 1) sum += __shfl_xor_sync(0xffffffffu, sum, o);
        float r = 1.f/sum; e0 *= r; e1 *= r;
        int f = f0 + i;
        sa[f*64+lane] = e0; sa[f*64+lane+32] = e1;
        ab[f*64+lane] = e0; ab[f*64+lane+32] = e1;
    }
    __syncwarp();
    float acc[8][4];
    #pragma unroll
    for (int i = 0; i < 8; i++) { acc[i][0]=acc[i][1]=acc[i][2]=acc[i][3]=0.f; }
    for (int g = 0; g < 64; g++) {
        float vv[4];
        #pragma unroll
        for (int j = 0; j < 4; j++) vv[j] = vs[g*STR + j*32 + lane];
        #pragma unroll
        for (int i = 0; i < 8; i++) {
            float av = sa[(f0+i)*64 + g];
            #pragma unroll
            for (int j = 0; j < 4; j++) acc[i][j] = fmaf(av, vv[j], acc[i][j]);
        }
    }
    #pragma unroll
    for (int i = 0; i < 8; i++)
        #pragma unroll
        for (int j = 0; j < 4; j++)
            attno[(size_t)(b*SEQ + f0 + i)*EMB + h*128 + j*32 + lane] = acc[i][j];
}

// ------------- mean over heads of attn -> x2_attn ---------------------------
__global__ void attn_mean_kernel(const float* __restrict__ attn, float* __restrict__ out)
{
    int i = blockIdx.x*256 + threadIdx.x;     // 131072 total
    int b = i >> 12, r = i & 4095;
    const float* p = attn + (size_t)b*4*4096 + r;
    out[i] = 0.25f*(p[0] + p[4096] + p[8192] + p[12288]);
}

// ------------- layernorm over last dim (512) --------------------------------
__global__ void __launch_bounds__(128) ln_kernel(
    const float* __restrict__ in, const float* __restrict__ gw,
    const float* __restrict__ bw, float* __restrict__ out)
{
    int t = blockIdx.x, tid = threadIdx.x;
    const float* r = in + (size_t)t*EMB;
    float v[4];
    #pragma unroll
    for (int i = 0; i < 4; i++) v[i] = r[tid + i*128];
    float s  = v[0]+v[1]+v[2]+v[3];
    float s2 = v[0]*v[0]+v[1]*v[1]+v[2]*v[2]+v[3]*v[3];
    for (int o = 16; o; o >>= 1) {
        s  += __shfl_xor_sync(0xffffffffu, s,  o);
        s2 += __shfl_xor_sync(0xffffffffu, s2, o);
    }
    __shared__ float rs[4], rs2[4];
    int w = tid>>5, lane = tid&31;
    if (lane == 0) { rs[w] = s; rs2[w] = s2; }
    __syncthreads();
    s  = rs[0]+rs[1]+rs[2]+rs[3];
    s2 = rs2[0]+rs2[1]+rs2[2]+rs2[3];
    float mean = s*(1.f/512.f);
    float var  = s2*(1.f/512.f) - mean*mean;
    float inv  = rsqrtf(var + 1e-5f);
    #pragma unroll
    for (int i = 0; i < 4; i++) {
        int c = tid + i*128;
        out[(size_t)t*EMB + c] = (v[i]-mean)*inv*gw[c] + bw[c];
    }
}

// ------------- pair MLPs: diff1/diff2 via factored y = x@W1^T ---------------
__global__ void __launch_bounds__(256) pair_kernel(
    const float* __restrict__ ybig,
    const float* __restrict__ a1, const float* __restrict__ a2,
    const float* __restrict__ b11, const float* __restrict__ w12, const float* __restrict__ b12,
    const float* __restrict__ b21, const float* __restrict__ w22, const float* __restrict__ b22,
    float* __restrict__ o1, float* __restrict__ o2)
{
    extern __shared__ float sm[];
    float* sy1 = sm;            // 64*128
    float* sy2 = sy1 + 8192;    // 64*128
    float* sb1 = sy2 + 8192;
    float* sw1 = sb1 + 128;
    float* sb2 = sw1 + 128;
    float* sw2 = sb2 + 128;
    int b = blockIdx.x, tid = threadIdx.x;
    for (int i = tid; i < 8192; i += 256) {
        int r = i >> 7, c = i & 127;
        const float* rp = ybig + (size_t)(b*64 + r)*NBIG;
        sy1[i] = rp[1536 + c];
        sy2[i] = rp[1664 + c];
    }
    if (tid < 128) { sb1[tid]=b11[tid]; sw1[tid]=w12[tid]; sb2[tid]=b21[tid]; sw2[tid]=w22[tid]; }
    __syncthreads();
    float bias1 = b12[0], bias2 = b22[0];
    int w = tid>>5, lane = tid&31;
    for (int p = w; p < 4096; p += 8) {
        int f = p >> 6, g = p & 63;
        float av1 = a1[(size_t)b*4096 + p];
        float av2 = a2[(size_t)b*4096 + p];
        const float* yg1 = sy1 + g*128; const float* yf1 = sy1 + f*128;
        const float* yg2 = sy2 + g*128; const float* yf2 = sy2 + f*128;
        float acc1 = 0.f, acc2 = 0.f;
        #pragma unroll
        for (int j = 0; j < 4; j++) {
            int c = j*32 + lane;
            float h1 = fmaf(av1, yg1[c]-yf1[c], sb1[c]);
            acc1 = fmaf(fmaxf(h1, 0.f), sw1[c], acc1);
            float h2 = fmaf(av2, yg2[c]-yf2[c], sb2[c]);
            acc2 = fmaf(fmaxf(h2, 0.f), sw2[c], acc2);
        }
        for (int o = 16; o; o >>= 1) {
            acc1 += __shfl_xor_sync(0xffffffffu, acc1, o);
            acc2 += __shfl_xor_sync(0xffffffffu, acc2, o);
        }
        if (lane == 0) {
            o1[(size_t)b*4096 + p] = fmaxf(acc1 + bias1, 0.f);
            o2[(size_t)b*4096 + p] = fmaxf(acc2 + bias2, 0.f);
        }
    }
}

// ---------------------------------------------------------------------------
extern "C" void kernel_launch(void* const* d_in, const int* in_sizes, int n_in,
                              void* d_out, int out_size)
{
    const float* x    = (const float*)d_in[0];
    const float* Wqkv = (const float*)d_in[1];
    const float* bqkv = (const float*)d_in[2];
    const float* Wo   = (const float*)d_in[3];
    const float* bo   = (const float*)d_in[4];
    const float* W1   = (const float*)d_in[5];
    const float* b1   = (const float*)d_in[6];
    const float* W2   = (const float*)d_in[7];
    const float* b2   = (const float*)d_in[8];
    const float* g1   = (const float*)d_in[9];
    const float* be1  = (const float*)d_in[10];
    const float* g2   = (const float*)d_in[11];
    const float* be2  = (const float*)d_in[12];
    const float* d1W1 = (const float*)d_in[13];
    const float* d1b1 = (const float*)d_in[14];
    const float* d1W2 = (const float*)d_in[15];
    const float* d1b2 = (const float*)d_in[16];
    const float* d2W1 = (const float*)d_in[17];
    const float* d2b1 = (const float*)d_in[18];
    const float* d2W2 = (const float*)d_in[19];
    const float* d2b2 = (const float*)d_in[20];

    float* out = (float*)d_out;
    float* A1 = out + 1048576;   // x1_attn (N,1,S,S)
    float* A2 = A1 + 131072;     // x2_attn
    float* D1 = A2 + 131072;     // diff1
    float* D2 = D1 + 131072;     // diff2

    float *p_big, *p_wbig, *p_bbig, *p_attn, *p_attno, *p_xres, *p_h, *p_ln1, *p_h2;
    cudaGetSymbolAddress((void**)&p_big,   g_big);
    cudaGetSymbolAddress((void**)&p_wbig,  g_wbig);
    cudaGetSymbolAddress((void**)&p_bbig,  g_bbig);
    cudaGetSymbolAddress((void**)&p_attn,  g_attn);
    cudaGetSymbolAddress((void**)&p_attno, g_attno);
    cudaGetSymbolAddress((void**)&p_xres,  g_xres);
    cudaGetSymbolAddress((void**)&p_h,     g_h);
    cudaGetSymbolAddress((void**)&p_ln1,   g_ln1);
    cudaGetSymbolAddress((void**)&p_h2,    g_h2);

    const int X1_SMEM   = (64*513 + 4096 + 64) * 4;   // 147968
    const int MHA_SMEM  = (3*64*129 + 4096) * 4;      // 115456
    const int PAIR_SMEM = (2*8192 + 4*128) * 4;       // 67584
    cudaFuncSetAttribute(x1_kernel,   cudaFuncAttributeMaxDynamicSharedMemorySize, X1_SMEM);
    cudaFuncSetAttribute(mha_kernel,  cudaFuncAttributeMaxDynamicSharedMemorySize, MHA_SMEM);
    cudaFuncSetAttribute(pair_kernel, cudaFuncAttributeMaxDynamicSharedMemorySize, PAIR_SMEM);

    // 0. pack merged projection weights/bias (device-to-device, capturable)
    cudaMemcpyAsync(p_wbig,              Wqkv, (size_t)1536*512*4, cudaMemcpyDeviceToDevice);
    cudaMemcpyAsync(p_wbig + 1536*512,   d1W1, (size_t)128*512*4,  cudaMemcpyDeviceToDevice);
    cudaMemcpyAsync(p_wbig + 1664*512,   d2W1, (size_t)128*512*4,  cudaMemcpyDeviceToDevice);
    pack_bias_kernel<<<7, 256>>>(bqkv, p_bbig);

    // 1. merged projection: [qkv | y1 | y2] = x @ Wbig^T + bbig
    gemm_nt<<<dim3(NBIG/64, 16), 256>>>(x, 512, p_wbig, 512, p_big, NBIG,
                                        p_bbig, nullptr, 0, 512, 0);
    // 2. x1 branch: Gram -> softmax -> x1 (xres cols [0,512)) + x1_attn
    x1_kernel<<<32, 256, X1_SMEM>>>(x, A1, p_xres);
    // 3. per-head attention
    mha_kernel<<<128, 256, MHA_SMEM>>>(p_big, p_attn, p_attno);
    // 4. mean over heads -> x2_attn
    attn_mean_kernel<<<512, 256>>>(p_attn, A2);
    // 5. out-proj -> xres cols [512,1024)
    gemm_nt<<<dim3(8, 16), 256>>>(p_attno, 512, Wo, 512, p_xres + 512, 1024,
                                  bo, nullptr, 0, 512, 0);
    // 6. fc1: h = x + relu(xres @ W1^T + b1)
    gemm_nt<<<dim3(8, 16), 256>>>(p_xres, 1024, W1, 1024, p_h, 512,
                                  b1, x, 512, 1024, 1);
    // 7. LN1
    ln_kernel<<<2048, 128>>>(p_h, g1, be1, p_ln1);
    // 8. fc2: h2 = ln1 + relu(ln1 @ W2^T + b2)
    gemm_nt<<<dim3(8, 16), 256>>>(p_ln1, 512, W2, 512, p_h2, 512,
                                  b2, p_ln1, 512, 512, 1);
    // 9. LN2 -> out
    ln_kernel<<<2048, 128>>>(p_h2, g2, be2, out);
    // 10. pair MLPs -> diff1/diff2 (y1,y2 read from merged buffer)
    pair_kernel<<<32, 256, PAIR_SMEM>>>(p_big, A1, A2,
                                        d1b1, d1W2, d1b2, d2b1, d2W2, d2b2, D1, D2);
}

// round 7
// speedup vs baseline: 2.7495x; 1.3596x over previous
#include <cuda_runtime.h>
#include <cstdint>

// Problem constants
#define NB 32
#define SEQ 64
#define EMB 512
#define NH 4
#define NTOK (NB*SEQ)          // 2048
#define NBIG 1792              // 1536 (qkv) + 128 (d1W1) + 128 (d2W1)

// ---------------- device scratch (no runtime alloc allowed) ----------------
__device__ float g_big  [NTOK*NBIG];     // qkv | y1 | y2
__device__ float g_wbig [NBIG*EMB];
__device__ float g_bbig [NBIG];
__device__ float g_attn [NB*NH*SEQ*SEQ];
__device__ float g_attno[NTOK*EMB];
__device__ float g_xres [NTOK*1024];
__device__ float g_h    [NTOK*EMB];
__device__ float g_ln1  [NTOK*EMB];
__device__ float g_h2   [NTOK*EMB];

// ---------------- packed-fp32 helpers (FFMA2 via PTX) -----------------------
__device__ __forceinline__ unsigned long long ffma2(
    unsigned long long a, unsigned long long b, unsigned long long c)
{
    unsigned long long d;
    asm("fma.rn.f32x2 %0, %1, %2, %3;" : "=l"(d) : "l"(a), "l"(b), "l"(c));
    return d;
}
__device__ __forceinline__ unsigned long long bcast2(float x)
{
    unsigned long long d;
    asm("mov.b64 %0, {%1, %1};" : "=l"(d) : "f"(x));
    return d;
}
__device__ __forceinline__ void unpack2(unsigned long long d, float& lo, float& hi)
{
    asm("mov.b64 {%0, %1}, %2;" : "=f"(lo), "=f"(hi) : "l"(d));
}

// ---- bias assembly: bqkv | zeros(256) --------------------------------------
__global__ void pack_bias_kernel(const float* __restrict__ bqkv, float* __restrict__ bbig)
{
    int i = blockIdx.x*256 + threadIdx.x;
    if (i < NBIG) bbig[i] = (i < 1536) ? bqkv[i] : 0.f;
}

// ---------------- big GEMM: BM=128, BN=128, BK=16, FFMA2 --------------------
// C[m,n] = sum_k A[m,k]*B[n,k] + bias[n]
__global__ void __launch_bounds__(256, 2) gemm_big(
    const float* __restrict__ A, int lda,
    const float* __restrict__ B, int ldb,
    float* __restrict__ C, int ldc,
    const float* __restrict__ bias, int K)
{
    __shared__ float As[2][16][128];
    __shared__ float Bs[2][16][128];
    int bm = blockIdx.y << 7, bn = blockIdx.x << 7;
    int tid = threadIdx.x;
    int ty = tid >> 4, tx = tid & 15;
    int lr = tid >> 2, lk = (tid & 3) << 2;

    const float* Ap0 = A + (size_t)(bm + lr) * lda + lk;
    const float* Ap1 = Ap0 + (size_t)64 * lda;
    const float* Bp0 = B + (size_t)(bn + lr) * ldb + lk;
    const float* Bp1 = Bp0 + (size_t)64 * ldb;

    unsigned long long acc[4][8];
    #pragma unroll
    for (int i = 0; i < 4; i++)
        #pragma unroll
        for (int j = 0; j < 8; j++) acc[i][j] = 0ull;

    {
        float4 a0 = *(const float4*)Ap0;
        float4 a1 = *(const float4*)Ap1;
        float4 b0 = *(const float4*)Bp0;
        float4 b1 = *(const float4*)Bp1;
        As[0][lk+0][lr]    = a0.x; As[0][lk+1][lr]    = a0.y;
        As[0][lk+2][lr]    = a0.z; As[0][lk+3][lr]    = a0.w;
        As[0][lk+0][lr+64] = a1.x; As[0][lk+1][lr+64] = a1.y;
        As[0][lk+2][lr+64] = a1.z; As[0][lk+3][lr+64] = a1.w;
        Bs[0][lk+0][lr]    = b0.x; Bs[0][lk+1][lr]    = b0.y;
        Bs[0][lk+2][lr]    = b0.z; Bs[0][lk+3][lr]    = b0.w;
        Bs[0][lk+0][lr+64] = b1.x; Bs[0][lk+1][lr+64] = b1.y;
        Bs[0][lk+2][lr+64] = b1.z; Bs[0][lk+3][lr+64] = b1.w;
    }
    __syncthreads();

    int nk = K >> 4;
    for (int c = 0; c < nk; ++c) {
        int cur = c & 1;
        float4 na0, na1, nb0, nb1;
        bool more = (c + 1 < nk);
        if (more) {
            int ko = (c + 1) << 4;
            na0 = *(const float4*)(Ap0 + ko);
            na1 = *(const float4*)(Ap1 + ko);
            nb0 = *(const float4*)(Bp0 + ko);
            nb1 = *(const float4*)(Bp1 + ko);
        }
        #pragma unroll
        for (int k = 0; k < 16; ++k) {
            ulonglong2 a01 = *(const ulonglong2*)&As[cur][k][ty*8];
            ulonglong2 a23 = *(const ulonglong2*)&As[cur][k][ty*8 + 4];
            float4 bf0 = *(const float4*)&Bs[cur][k][tx*8];
            float4 bf1 = *(const float4*)&Bs[cur][k][tx*8 + 4];
            unsigned long long ap[4] = {a01.x, a01.y, a23.x, a23.y};
            unsigned long long bd[8] = {bcast2(bf0.x), bcast2(bf0.y), bcast2(bf0.z), bcast2(bf0.w),
                                        bcast2(bf1.x), bcast2(bf1.y), bcast2(bf1.z), bcast2(bf1.w)};
            #pragma unroll
            for (int i = 0; i < 4; i++)
                #pragma unroll
                for (int j = 0; j < 8; j++)
                    acc[i][j] = ffma2(ap[i], bd[j], acc[i][j]);
        }
        if (more) {
            int nb = cur ^ 1;
            As[nb][lk+0][lr]    = na0.x; As[nb][lk+1][lr]    = na0.y;
            As[nb][lk+2][lr]    = na0.z; As[nb][lk+3][lr]    = na0.w;
            As[nb][lk+0][lr+64] = na1.x; As[nb][lk+1][lr+64] = na1.y;
            As[nb][lk+2][lr+64] = na1.z; As[nb][lk+3][lr+64] = na1.w;
            Bs[nb][lk+0][lr]    = nb0.x; Bs[nb][lk+1][lr]    = nb0.y;
            Bs[nb][lk+2][lr]    = nb0.z; Bs[nb][lk+3][lr]    = nb0.w;
            Bs[nb][lk+0][lr+64] = nb1.x; Bs[nb][lk+1][lr+64] = nb1.y;
            Bs[nb][lk+2][lr+64] = nb1.z; Bs[nb][lk+3][lr+64] = nb1.w;
            __syncthreads();
        }
    }

    int n0 = bn + tx*8;
    float bv[8] = {0,0,0,0,0,0,0,0};
    if (bias) {
        float4 t0 = *(const float4*)&bias[n0];
        float4 t1 = *(const float4*)&bias[n0 + 4];
        bv[0]=t0.x; bv[1]=t0.y; bv[2]=t0.z; bv[3]=t0.w;
        bv[4]=t1.x; bv[5]=t1.y; bv[6]=t1.z; bv[7]=t1.w;
    }
    #pragma unroll
    for (int i2 = 0; i2 < 4; i2++) {
        float r0[8], r1[8];
        #pragma unroll
        for (int j = 0; j < 8; j++) {
            unpack2(acc[i2][j], r0[j], r1[j]);
            r0[j] += bv[j]; r1[j] += bv[j];
        }
        int m0 = bm + ty*8 + i2*2;
        *(float4*)&C[(size_t)m0*ldc + n0]       = make_float4(r0[0],r0[1],r0[2],r0[3]);
        *(float4*)&C[(size_t)m0*ldc + n0 + 4]   = make_float4(r0[4],r0[5],r0[6],r0[7]);
        *(float4*)&C[(size_t)(m0+1)*ldc + n0]   = make_float4(r1[0],r1[1],r1[2],r1[3]);
        *(float4*)&C[(size_t)(m0+1)*ldc + n0+4] = make_float4(r1[4],r1[5],r1[6],r1[7]);
    }
}

// ---------------- GEMM: BM=128, BN=64, BK=16, FFMA2 -------------------------
// mode 0: C = acc + bias ; mode 1: C = resid + relu(acc + bias)
__global__ void __launch_bounds__(256, 2) gemm_nt(
    const float* __restrict__ A, int lda,
    const float* __restrict__ B, int ldb,
    float* __restrict__ C, int ldc,
    const float* __restrict__ bias,
    const float* __restrict__ resid, int ldr,
    int K, int mode)
{
    __shared__ float As[2][16][128];
    __shared__ float Bs[2][16][64];
    int bm = blockIdx.y << 7, bn = blockIdx.x << 6;
    int tid = threadIdx.x;
    int ty = tid >> 4, tx = tid & 15;
    int lr = tid >> 2, lk = (tid & 3) << 2;

    const float* Ap0 = A + (size_t)(bm + lr) * lda + lk;
    const float* Ap1 = Ap0 + (size_t)64 * lda;
    const float* Bp  = B + (size_t)(bn + lr) * ldb + lk;

    unsigned long long acc[4][4];
    #pragma unroll
    for (int i = 0; i < 4; i++)
        #pragma unroll
        for (int j = 0; j < 4; j++) acc[i][j] = 0ull;

    {
        float4 a0 = *(const float4*)Ap0;
        float4 a1 = *(const float4*)Ap1;
        float4 b0 = *(const float4*)Bp;
        As[0][lk+0][lr]    = a0.x; As[0][lk+1][lr]    = a0.y;
        As[0][lk+2][lr]    = a0.z; As[0][lk+3][lr]    = a0.w;
        As[0][lk+0][lr+64] = a1.x; As[0][lk+1][lr+64] = a1.y;
        As[0][lk+2][lr+64] = a1.z; As[0][lk+3][lr+64] = a1.w;
        Bs[0][lk+0][lr] = b0.x; Bs[0][lk+1][lr] = b0.y;
        Bs[0][lk+2][lr] = b0.z; Bs[0][lk+3][lr] = b0.w;
    }
    __syncthreads();

    int nk = K >> 4;
    for (int c = 0; c < nk; ++c) {
        int cur = c & 1;
        float4 na0, na1, nb0;
        bool more = (c + 1 < nk);
        if (more) {
            int ko = (c + 1) << 4;
            na0 = *(const float4*)(Ap0 + ko);
            na1 = *(const float4*)(Ap1 + ko);
            nb0 = *(const float4*)(Bp  + ko);
        }
        #pragma unroll
        for (int k = 0; k < 16; ++k) {
            ulonglong2 a01 = *(const ulonglong2*)&As[cur][k][ty*8];
            ulonglong2 a23 = *(const ulonglong2*)&As[cur][k][ty*8 + 4];
            float4 bf = *(const float4*)&Bs[cur][k][tx*4];
            unsigned long long ap[4] = {a01.x, a01.y, a23.x, a23.y};
            unsigned long long bd[4] = {bcast2(bf.x), bcast2(bf.y), bcast2(bf.z), bcast2(bf.w)};
            #pragma unroll
            for (int i = 0; i < 4; i++)
                #pragma unroll
                for (int j = 0; j < 4; j++)
                    acc[i][j] = ffma2(ap[i], bd[j], acc[i][j]);
        }
        if (more) {
            int nb = cur ^ 1;
            As[nb][lk+0][lr]    = na0.x; As[nb][lk+1][lr]    = na0.y;
            As[nb][lk+2][lr]    = na0.z; As[nb][lk+3][lr]    = na0.w;
            As[nb][lk+0][lr+64] = na1.x; As[nb][lk+1][lr+64] = na1.y;
            As[nb][lk+2][lr+64] = na1.z; As[nb][lk+3][lr+64] = na1.w;
            Bs[nb][lk+0][lr] = nb0.x; Bs[nb][lk+1][lr] = nb0.y;
            Bs[nb][lk+2][lr] = nb0.z; Bs[nb][lk+3][lr] = nb0.w;
            __syncthreads();
        }
    }

    int n = bn + tx*4;
    float4 bv = make_float4(0.f,0.f,0.f,0.f);
    if (bias) bv = *(const float4*)&bias[n];
    #pragma unroll
    for (int i2 = 0; i2 < 4; i2++) {
        float r0[4], r1[4];
        #pragma unroll
        for (int j = 0; j < 4; j++) unpack2(acc[i2][j], r0[j], r1[j]);
        int m0 = bm + ty*8 + i2*2;
        float4 v0 = make_float4(r0[0]+bv.x, r0[1]+bv.y, r0[2]+bv.z, r0[3]+bv.w);
        float4 v1 = make_float4(r1[0]+bv.x, r1[1]+bv.y, r1[2]+bv.z, r1[3]+bv.w);
        if (mode == 1) {
            float4 ra = *(const float4*)&resid[(size_t)m0*ldr + n];
            float4 rb = *(const float4*)&resid[(size_t)(m0+1)*ldr + n];
            v0.x = ra.x + fmaxf(v0.x,0.f); v0.y = ra.y + fmaxf(v0.y,0.f);
            v0.z = ra.z + fmaxf(v0.z,0.f); v0.w = ra.w + fmaxf(v0.w,0.f);
            v1.x = rb.x + fmaxf(v1.x,0.f); v1.y = rb.y + fmaxf(v1.y,0.f);
            v1.z = rb.z + fmaxf(v1.z,0.f); v1.w = rb.w + fmaxf(v1.w,0.f);
        }
        *(float4*)&C[(size_t)m0*ldc + n]     = v0;
        *(float4*)&C[(size_t)(m0+1)*ldc + n] = v1;
    }
}

// -------- x1 path: Gram -> -L2/T softmax -> x1 = attn @ x -------------------
// 64 blocks: block = (batch, half); each handles 32 f-rows (4 per warp).
__global__ void __launch_bounds__(256) x1_kernel(
    const float* __restrict__ x, float* __restrict__ a_out, float* __restrict__ xres)
{
    extern __shared__ float sm[];
    const int STR = 516;                 // pad 4: float4-aligned, conflict-free
    float* xs   = sm;                    // 64*516
    float* sa   = xs + 64*STR;           // 32*64 local attn rows
    float* snrm = sa + 32*64;            // 64 norms
    int b = blockIdx.x >> 1, half = blockIdx.x & 1;
    int tid = threadIdx.x;
    const float* xb = x + (size_t)b*SEQ*EMB;
    for (int i = tid; i < SEQ*EMB; i += 256)
        xs[(i>>9)*STR + (i&511)] = xb[i];
    __syncthreads();

    // norms: 4 threads per row
    {
        int t = tid >> 2, sub = tid & 3;
        float s = 0.f;
        #pragma unroll 8
        for (int j = 0; j < 128; j++) {
            float v = xs[t*STR + sub + 4*j];
            s = fmaf(v, v, s);
        }
        s += __shfl_xor_sync(0xffffffffu, s, 1);
        s += __shfl_xor_sync(0xffffffffu, s, 2);
        if (sub == 0) snrm[t] = s;
    }

    int w = tid>>5, lane = tid&31;
    int fl0 = w*4;                        // local f rows fl0..fl0+3
    int fbase = half*32;                  // global offset

    // Gram: rows (fbase+fl) x all g, vectorized over e
    float acc0[4] = {}, acc1[4] = {};
    for (int e4 = 0; e4 < 128; e4++) {
        float4 g0 = *(const float4*)&xs[lane*STR + 4*e4];
        float4 g1 = *(const float4*)&xs[(lane+32)*STR + 4*e4];
        #pragma unroll
        for (int i = 0; i < 4; i++) {
            float4 fv = *(const float4*)&xs[(fbase+fl0+i)*STR + 4*e4];
            acc0[i] = fmaf(fv.x,g0.x, fmaf(fv.y,g0.y, fmaf(fv.z,g0.z, fmaf(fv.w,g0.w, acc0[i]))));
            acc1[i] = fmaf(fv.x,g1.x, fmaf(fv.y,g1.y, fmaf(fv.z,g1.z, fmaf(fv.w,g1.w, acc1[i]))));
        }
    }
    #pragma unroll
    for (int i = 0; i < 4; i++) {
        sa[(fl0+i)*64 + lane]      = acc0[i];
        sa[(fl0+i)*64 + lane + 32] = acc1[i];
    }
    __syncthreads();

    const float invT = 1.f/13.544f;
    float* ab = a_out + (size_t)b*4096;
    #pragma unroll
    for (int i = 0; i < 4; i++) {
        int fl = fl0 + i, f = fbase + fl;
        float nf = snrm[f];
        float s0 = (2.f*sa[fl*64+lane]    - nf - snrm[lane])    * invT;
        float s1 = (2.f*sa[fl*64+lane+32] - nf - snrm[lane+32]) * invT;
        float m = fmaxf(s0, s1);
        for (int o = 16; o; o >>= 1) m = fmaxf(m, __shfl_xor_sync(0xffffffffu, m, o));
        float e0 = __expf(s0 - m), e1 = __expf(s1 - m);
        float sum = e0 + e1;
        for (int o = 16; o; o >>= 1) sum += __shfl_xor_sync(0xffffffffu, sum, o);
        float r = 1.f/sum; e0 *= r; e1 *= r;
        sa[fl*64+lane] = e0; sa[fl*64+lane+32] = e1;
        ab[f*64+lane] = e0;  ab[f*64+lane+32] = e1;
    }
    __syncwarp();

    // x1[f,e] = sum_g a[f,g]*x[g,e]
    for (int ec = 0; ec < 4; ec++) {
        float acc[4][4];
        #pragma unroll
        for (int i = 0; i < 4; i++) { acc[i][0]=acc[i][1]=acc[i][2]=acc[i][3]=0.f; }
        for (int g4 = 0; g4 < 16; g4++) {
            float sarr[4][4];
            #pragma unroll
            for (int i = 0; i < 4; i++)
                *(float4*)sarr[i] = *(const float4*)&sa[(fl0+i)*64 + 4*g4];
            #pragma unroll
            for (int jj = 0; jj < 4; jj++) {
                int g = 4*g4 + jj;
                float vv[4];
                #pragma unroll
                for (int j = 0; j < 4; j++) vv[j] = xs[g*STR + ec*128 + j*32 + lane];
                #pragma unroll
                for (int i = 0; i < 4; i++)
                    #pragma unroll
                    for (int j = 0; j < 4; j++)
                        acc[i][j] = fmaf(sarr[i][jj], vv[j], acc[i][j]);
            }
        }
        #pragma unroll
        for (int i = 0; i < 4; i++)
            #pragma unroll
            for (int j = 0; j < 4; j++)
                xres[(size_t)(b*SEQ + fbase + fl0 + i)*1024 + ec*128 + j*32 + lane] = acc[i][j];
    }
}

// -------------- MHA core: per (b,h): softmax(QK^T/sqrt(hd)) @ V ------------
__global__ void __launch_bounds__(256) mha_kernel(
    const float* __restrict__ qkv, float* __restrict__ attn_g, float* __restrict__ attno)
{
    extern __shared__ float sm[];
    const int STR = 132;
    float* qs = sm;
    float* ks = qs + 64*STR;
    float* vs = ks + 64*STR;
    float* sa = vs + 64*STR;             // 64*64 attn
    int b = blockIdx.x >> 2, h = blockIdx.x & 3;
    int tid = threadIdx.x;
    const float* base = qkv + (size_t)b*SEQ*NBIG + h*128;
    for (int i = tid; i < 64*128; i += 256) {
        int r = i >> 7, c = i & 127;
        const float* rp = base + (size_t)r*NBIG;
        qs[r*STR+c] = rp[c];
        ks[r*STR+c] = rp[512 + c];
        vs[r*STR+c] = rp[1024 + c];
    }
    __syncthreads();
    int w = tid>>5, lane = tid&31, f0 = w*8;
    float acc0[8] = {}, acc1[8] = {};
    for (int e4 = 0; e4 < 32; e4++) {
        float4 k0 = *(const float4*)&ks[lane*STR + 4*e4];
        float4 k1 = *(const float4*)&ks[(lane+32)*STR + 4*e4];
        #pragma unroll
        for (int i = 0; i < 8; i++) {
            float4 qv = *(const float4*)&qs[(f0+i)*STR + 4*e4];
            acc0[i] = fmaf(qv.x,k0.x, fmaf(qv.y,k0.y, fmaf(qv.z,k0.z, fmaf(qv.w,k0.w, acc0[i]))));
            acc1[i] = fmaf(qv.x,k1.x, fmaf(qv.y,k1.y, fmaf(qv.z,k1.z, fmaf(qv.w,k1.w, acc1[i]))));
        }
    }
    const float scale = 0.088388347648318447f;  // 1/sqrt(128)
    float* ab = attn_g + (size_t)(b*4 + h)*4096;
    #pragma unroll
    for (int i = 0; i < 8; i++) {
        float s0 = acc0[i]*scale, s1 = acc1[i]*scale;
        float m = fmaxf(s0, s1);
        for (int o = 16; o; o >>= 1) m = fmaxf(m, __shfl_xor_sync(0xffffffffu, m, o));
        float e0 = __expf(s0 - m), e1 = __expf(s1 - m);
        float sum = e0 + e1;
        for (int o = 16; o; o >>= 1) sum += __shfl_xor_sync(0xffffffffu, sum, o);
        float r = 1.f/sum; e0 *= r; e1 *= r;
        int f = f0 + i;
        sa[f*64+lane] = e0; sa[f*64+lane+32] = e1;
        ab[f*64+lane] = e0; ab[f*64+lane+32] = e1;
    }
    __syncwarp();
    float acc[8][4];
    #pragma unroll
    for (int i = 0; i < 8; i++) { acc[i][0]=acc[i][1]=acc[i][2]=acc[i][3]=0.f; }
    for (int g4 = 0; g4 < 16; g4++) {
        float sarr[8][4];
        #pragma unroll
        for (int i = 0; i < 8; i++)
            *(float4*)sarr[i] = *(const float4*)&sa[(f0+i)*64 + 4*g4];
        #pragma unroll
        for (int jj = 0; jj < 4; jj++) {
            int g = 4*g4 + jj;
            float vv[4];
            #pragma unroll
            for (int j = 0; j < 4; j++) vv[j] = vs[g*STR + j*32 + lane];
            #pragma unroll
            for (int i = 0; i < 8; i++)
                #pragma unroll
                for (int j = 0; j < 4; j++)
                    acc[i][j] = fmaf(sarr[i][jj], vv[j], acc[i][j]);
        }
    }
    #pragma unroll
    for (int i = 0; i < 8; i++)
        #pragma unroll
        for (int j = 0; j < 4; j++)
            attno[(size_t)(b*SEQ + f0 + i)*EMB + h*128 + j*32 + lane] = acc[i][j];
}

// ------------- mean over heads of attn -> x2_attn ---------------------------
__global__ void attn_mean_kernel(const float* __restrict__ attn, float* __restrict__ out)
{
    int i = blockIdx.x*256 + threadIdx.x;     // 32768 float4s total
    int b = i >> 10, r = i & 1023;
    const float4* p = (const float4*)(attn + (size_t)b*16384) + r;
    float4 a = p[0], c = p[1024], d = p[2048], e = p[3072];
    float4 o;
    o.x = 0.25f*(a.x+c.x+d.x+e.x); o.y = 0.25f*(a.y+c.y+d.y+e.y);
    o.z = 0.25f*(a.z+c.z+d.z+e.z); o.w = 0.25f*(a.w+c.w+d.w+e.w);
    ((float4*)out)[i] = o;
}

// ------------- layernorm over last dim (512) --------------------------------
__global__ void __launch_bounds__(128) ln_kernel(
    const float* __restrict__ in, const float* __restrict__ gw,
    const float* __restrict__ bw, float* __restrict__ out)
{
    int t = blockIdx.x, tid = threadIdx.x;
    const float* r = in + (size_t)t*EMB;
    float v[4];
    #pragma unroll
    for (int i = 0; i < 4; i++) v[i] = r[tid + i*128];
    float s  = v[0]+v[1]+v[2]+v[3];
    float s2 = v[0]*v[0]+v[1]*v[1]+v[2]*v[2]+v[3]*v[3];
    for (int o = 16; o; o >>= 1) {
        s  += __shfl_xor_sync(0xffffffffu, s,  o);
        s2 += __shfl_xor_sync(0xffffffffu, s2, o);
    }
    __shared__ float rs[4], rs2[4];
    int w = tid>>5, lane = tid&31;
    if (lane == 0) { rs[w] = s; rs2[w] = s2; }
    __syncthreads();
    s  = rs[0]+rs[1]+rs[2]+rs[3];
    s2 = rs2[0]+rs2[1]+rs2[2]+rs2[3];
    float mean = s*(1.f/512.f);
    float var  = s2*(1.f/512.f) - mean*mean;
    float inv  = rsqrtf(var + 1e-5f);
    #pragma unroll
    for (int i = 0; i < 4; i++) {
        int c = tid + i*128;
        out[(size_t)t*EMB + c] = (v[i]-mean)*inv*gw[c] + bw[c];
    }
}

// ------------- pair MLPs: diff1/diff2 via factored y = x@W1^T ---------------
// 128 blocks: block = (batch, quarter of pairs)
__global__ void __launch_bounds__(256) pair_kernel(
    const float* __restrict__ ybig,
    const float* __restrict__ a1, const float* __restrict__ a2,
    const float* __restrict__ b11, const float* __restrict__ w12, const float* __restrict__ b12,
    const float* __restrict__ b21, const float* __restrict__ w22, const float* __restrict__ b22,
    float* __restrict__ o1, float* __restrict__ o2)
{
    extern __shared__ float sm[];
    float* sy1 = sm;            // 64*128
    float* sy2 = sy1 + 8192;    // 64*128
    float* sb1 = sy2 + 8192;
    float* sw1 = sb1 + 128;
    float* sb2 = sw1 + 128;
    float* sw2 = sb2 + 128;
    int b = blockIdx.x >> 2, q = blockIdx.x & 3;
    int tid = threadIdx.x;
    for (int i = tid; i < 8192; i += 256) {
        int r = i >> 7, c = i & 127;
        const float* rp = ybig + (size_t)(b*64 + r)*NBIG;
        sy1[i] = rp[1536 + c];
        sy2[i] = rp[1664 + c];
    }
    if (tid < 128) { sb1[tid]=b11[tid]; sw1[tid]=w12[tid]; sb2[tid]=b21[tid]; sw2[tid]=w22[tid]; }
    __syncthreads();
    float bias1 = b12[0], bias2 = b22[0];
    int w = tid>>5, lane = tid&31;
    int p0 = q*1024, p1 = p0 + 1024;
    for (int p = p0 + w; p < p1; p += 8) {
        int f = p >> 6, g = p & 63;
        float av1 = a1[(size_t)b*4096 + p];
        float av2 = a2[(size_t)b*4096 + p];
        const float* yg1 = sy1 + g*128; const float* yf1 = sy1 + f*128;
        const float* yg2 = sy2 + g*128; const float* yf2 = sy2 + f*128;
        float acc1 = 0.f, acc2 = 0.f;
        #pragma unroll
        for (int j = 0; j < 4; j++) {
            int c = j*32 + lane;
            float h1 = fmaf(av1, yg1[c]-yf1[c], sb1[c]);
            acc1 = fmaf(fmaxf(h1, 0.f), sw1[c], acc1);
            float h2 = fmaf(av2, yg2[c]-yf2[c], sb2[c]);
            acc2 = fmaf(fmaxf(h2, 0.f), sw2[c], acc2);
        }
        for (int o = 16; o; o >>= 1) {
            acc1 += __shfl_xor_sync(0xffffffffu, acc1, o);
            acc2 += __shfl_xor_sync(0xffffffffu, acc2, o);
        }
        if (lane == 0) {
            o1[(size_t)b*4096 + p] = fmaxf(acc1 + bias1, 0.f);
            o2[(size_t)b*4096 + p] = fmaxf(acc2 + bias2, 0.f);
        }
    }
}

// ---------------------------------------------------------------------------
extern "C" void kernel_launch(void* const* d_in, const int* in_sizes, int n_in,
                              void* d_out, int out_size)
{
    const float* x    = (const float*)d_in[0];
    const float* Wqkv = (const float*)d_in[1];
    const float* bqkv = (const float*)d_in[2];
    const float* Wo   = (const float*)d_in[3];
    const float* bo   = (const float*)d_in[4];
    const float* W1   = (const float*)d_in[5];
    const float* b1   = (const float*)d_in[6];
    const float* W2   = (const float*)d_in[7];
    const float* b2   = (const float*)d_in[8];
    const float* g1   = (const float*)d_in[9];
    const float* be1  = (const float*)d_in[10];
    const float* g2   = (const float*)d_in[11];
    const float* be2  = (const float*)d_in[12];
    const float* d1W1 = (const float*)d_in[13];
    const float* d1b1 = (const float*)d_in[14];
    const float* d1W2 = (const float*)d_in[15];
    const float* d1b2 = (const float*)d_in[16];
    const float* d2W1 = (const float*)d_in[17];
    const float* d2b1 = (const float*)d_in[18];
    const float* d2W2 = (const float*)d_in[19];
    const float* d2b2 = (const float*)d_in[20];

    float* out = (float*)d_out;
    float* A1 = out + 1048576;   // x1_attn (N,1,S,S)
    float* A2 = A1 + 131072;     // x2_attn
    float* D1 = A2 + 131072;     // diff1
    float* D2 = D1 + 131072;     // diff2

    float *p_big, *p_wbig, *p_bbig, *p_attn, *p_attno, *p_xres, *p_h, *p_ln1, *p_h2;
    cudaGetSymbolAddress((void**)&p_big,   g_big);
    cudaGetSymbolAddress((void**)&p_wbig,  g_wbig);
    cudaGetSymbolAddress((void**)&p_bbig,  g_bbig);
    cudaGetSymbolAddress((void**)&p_attn,  g_attn);
    cudaGetSymbolAddress((void**)&p_attno, g_attno);
    cudaGetSymbolAddress((void**)&p_xres,  g_xres);
    cudaGetSymbolAddress((void**)&p_h,     g_h);
    cudaGetSymbolAddress((void**)&p_ln1,   g_ln1);
    cudaGetSymbolAddress((void**)&p_h2,    g_h2);

    const int X1_SMEM   = (64*516 + 32*64 + 64) * 4;  // 140544
    const int MHA_SMEM  = (3*64*132 + 4096) * 4;      // 117760
    const int PAIR_SMEM = (2*8192 + 4*128) * 4;       // 67584
    cudaFuncSetAttribute(x1_kernel,   cudaFuncAttributeMaxDynamicSharedMemorySize, X1_SMEM);
    cudaFuncSetAttribute(mha_kernel,  cudaFuncAttributeMaxDynamicSharedMemorySize, MHA_SMEM);
    cudaFuncSetAttribute(pair_kernel, cudaFuncAttributeMaxDynamicSharedMemorySize, PAIR_SMEM);

    // 0. pack merged projection weights/bias (device-to-device, capturable)
    cudaMemcpyAsync(p_wbig,              Wqkv, (size_t)1536*512*4, cudaMemcpyDeviceToDevice);
    cudaMemcpyAsync(p_wbig + 1536*512,   d1W1, (size_t)128*512*4,  cudaMemcpyDeviceToDevice);
    cudaMemcpyAsync(p_wbig + 1664*512,   d2W1, (size_t)128*512*4,  cudaMemcpyDeviceToDevice);
    pack_bias_kernel<<<7, 256>>>(bqkv, p_bbig);

    // 1. merged projection: [qkv | y1 | y2] = x @ Wbig^T + bbig
    gemm_big<<<dim3(NBIG/128, 16), 256>>>(x, 512, p_wbig, 512, p_big, NBIG, p_bbig, 512);
    // 2. x1 branch: Gram -> softmax -> x1 (xres cols [0,512)) + x1_attn
    x1_kernel<<<64, 256, X1_SMEM>>>(x, A1, p_xres);
    // 3. per-head attention
    mha_kernel<<<128, 256, MHA_SMEM>>>(p_big, p_attn, p_attno);
    // 4. mean over heads -> x2_attn
    attn_mean_kernel<<<128, 256>>>(p_attn, A2);
    // 5. out-proj -> xres cols [512,1024)
    gemm_nt<<<dim3(8, 16), 256>>>(p_attno, 512, Wo, 512, p_xres + 512, 1024,
                                  bo, nullptr, 0, 512, 0);
    // 6. fc1: h = x + relu(xres @ W1^T + b1)
    gemm_nt<<<dim3(8, 16), 256>>>(p_xres, 1024, W1, 1024, p_h, 512,
                                  b1, x, 512, 1024, 1);
    // 7. LN1
    ln_kernel<<<2048, 128>>>(p_h, g1, be1, p_ln1);
    // 8. fc2: h2 = ln1 + relu(ln1 @ W2^T + b2)
    gemm_nt<<<dim3(8, 16), 256>>>(p_ln1, 512, W2, 512, p_h2, 512,
                                  b2, p_ln1, 512, 512, 1);
    // 9. LN2 -> out
    ln_kernel<<<2048, 128>>>(p_h2, g2, be2, out);
    // 10. pair MLPs -> diff1/diff2 (y1,y2 read from merged buffer)
    pair_kernel<<<128, 256, PAIR_SMEM>>>(p_big, A1, A2,
                                         d1b1, d1W2, d1b2, d2b1, d2W2, d2b2, D1, D2);
}